// round 1
// baseline (speedup 1.0000x reference)
#include <cuda_runtime.h>
#include <cuda_bf16.h>
#include <math.h>

// Problem constants
#define Bn  2
#define Tn  2048
#define Cn  1024
#define Hn  16
#define HDn 64
#define QKV_N (3*Cn)          // 3072
#define Mrows (Bn*Tn)         // 4096

// Scratch (allocation-free: __device__ globals)
__device__ float g_qkv[(size_t)Mrows * QKV_N];   // [B*T, 3C]  48 MB
__device__ float g_y[(size_t)Mrows * Cn];        // [B*T, C]   32 MB

// ---------------------------------------------------------------------------
// SGEMM: C[M,N] = A[M,K] @ W[K,N] + bias[N]
// 128x128 tile, BK=8, 256 threads, 8x8 microtile. All dims multiples of tiles.
// ---------------------------------------------------------------------------
#define BM 128
#define BN 128
#define BK 8

__global__ __launch_bounds__(256)
void sgemm_bias(const float* __restrict__ A, const float* __restrict__ W,
                const float* __restrict__ bias, float* __restrict__ C,
                int M, int N, int K)
{
    __shared__ float As[BK][BM];
    __shared__ float Bs[BK][BN];

    const int tid = threadIdx.x;
    const int bm = blockIdx.y * BM;
    const int bn = blockIdx.x * BN;

    // A tile load: 128 rows x 8 k  -> one float4 per thread
    const int arow = tid >> 1;            // 0..127
    const int acol = (tid & 1) * 4;       // 0 or 4
    // W tile load: 8 k x 128 n -> one float4 per thread
    const int brow = tid >> 5;            // 0..7
    const int bcol = (tid & 31) * 4;      // 0..124

    const float* Aptr = A + (size_t)(bm + arow) * K + acol;
    const float* Wptr = W + (size_t)brow * N + bn + bcol;

    const int tx = tid & 15;              // n-dir
    const int ty = tid >> 4;              // m-dir
    const int mro = ty * 8;
    const int nco = tx * 8;

    float acc[8][8];
    #pragma unroll
    for (int i = 0; i < 8; i++)
        #pragma unroll
        for (int j = 0; j < 8; j++) acc[i][j] = 0.f;

    for (int k0 = 0; k0 < K; k0 += BK) {
        float4 av = *(const float4*)Aptr;  Aptr += BK;
        float4 wv = *(const float4*)Wptr;  Wptr += (size_t)BK * N;

        As[acol + 0][arow] = av.x;
        As[acol + 1][arow] = av.y;
        As[acol + 2][arow] = av.z;
        As[acol + 3][arow] = av.w;
        *(float4*)&Bs[brow][bcol] = wv;
        __syncthreads();

        #pragma unroll
        for (int kk = 0; kk < BK; kk++) {
            float a[8], b[8];
            *(float4*)&a[0] = *(const float4*)&As[kk][mro];
            *(float4*)&a[4] = *(const float4*)&As[kk][mro + 4];
            *(float4*)&b[0] = *(const float4*)&Bs[kk][nco];
            *(float4*)&b[4] = *(const float4*)&Bs[kk][nco + 4];
            #pragma unroll
            for (int i = 0; i < 8; i++)
                #pragma unroll
                for (int j = 0; j < 8; j++)
                    acc[i][j] = fmaf(a[i], b[j], acc[i][j]);
        }
        __syncthreads();
    }

    // Epilogue: add bias, store
    float bsv[8];
    *(float4*)&bsv[0] = *(const float4*)&bias[bn + nco];
    *(float4*)&bsv[4] = *(const float4*)&bias[bn + nco + 4];
    #pragma unroll
    for (int i = 0; i < 8; i++) {
        float* crow = C + (size_t)(bm + mro + i) * N + bn + nco;
        float4 o0, o1;
        o0.x = acc[i][0] + bsv[0]; o0.y = acc[i][1] + bsv[1];
        o0.z = acc[i][2] + bsv[2]; o0.w = acc[i][3] + bsv[3];
        o1.x = acc[i][4] + bsv[4]; o1.y = acc[i][5] + bsv[5];
        o1.z = acc[i][6] + bsv[6]; o1.w = acc[i][7] + bsv[7];
        *(float4*)&crow[0] = o0;
        *(float4*)&crow[4] = o1;
    }
}

// ---------------------------------------------------------------------------
// Flash attention, fp32, causal. One thread = one query row (q + acc in regs),
// K/V tiled through smem. Online softmax chunked by 8 keys to amortize the
// accumulator rescale.
// grid: (T/128, H, B), 128 threads.
// ---------------------------------------------------------------------------
#define BQ  128
#define BKV 64
#define SCALE 0.125f   // 1/sqrt(64)

__global__ __launch_bounds__(BQ)
void attn_kernel(const float* __restrict__ qkv, float* __restrict__ y)
{
    const int b  = blockIdx.z;
    const int h  = blockIdx.y;
    const int q0 = blockIdx.x * BQ;
    const int tid = threadIdx.x;
    const int qi  = q0 + tid;

    __shared__ float Ks[BKV][HDn];
    __shared__ float Vs[BKV][HDn];

    // Load this thread's q row (64 floats) into registers
    const float* qb = qkv + ((size_t)(b * Tn + qi)) * QKV_N + h * HDn;
    float4 qv[16];
    #pragma unroll
    for (int i = 0; i < 16; i++) qv[i] = *(const float4*)(qb + i * 4);

    float m = -INFINITY, l = 0.f;
    float4 acc[16];
    #pragma unroll
    for (int i = 0; i < 16; i++) acc[i] = make_float4(0.f, 0.f, 0.f, 0.f);

    const int kv_end = q0 + BQ;   // causal: no keys beyond last query of block
    for (int kt = 0; kt < kv_end; kt += BKV) {
        // Stage 64 K rows + 64 V rows into smem (coalesced 256B chunks)
        const float* kb = qkv + ((size_t)(b * Tn + kt)) * QKV_N + Cn   + h * HDn;
        const float* vb = qkv + ((size_t)(b * Tn + kt)) * QKV_N + 2*Cn + h * HDn;
        #pragma unroll
        for (int i = 0; i < 8; i++) {
            int f = i * BQ + tid;      // 0..1023
            int r = f >> 4;            // kv row 0..63
            int c = (f & 15) * 4;      // float offset
            *(float4*)&Ks[r][c] = *(const float4*)(kb + (size_t)r * QKV_N + c);
            *(float4*)&Vs[r][c] = *(const float4*)(vb + (size_t)r * QKV_N + c);
        }
        __syncthreads();

        #pragma unroll 1
        for (int jc = 0; jc < BKV; jc += 8) {
            // 1) scores for 8 keys
            float s[8];
            #pragma unroll
            for (int jj = 0; jj < 8; jj++) {
                const int j = jc + jj;
                float dot = 0.f;
                #pragma unroll
                for (int i = 0; i < 16; i++) {
                    float4 kv4 = *(const float4*)&Ks[j][i * 4];
                    dot = fmaf(qv[i].x, kv4.x, dot);
                    dot = fmaf(qv[i].y, kv4.y, dot);
                    dot = fmaf(qv[i].z, kv4.z, dot);
                    dot = fmaf(qv[i].w, kv4.w, dot);
                }
                s[jj] = (kt + j <= qi) ? dot * SCALE : -INFINITY;
            }
            // 2) chunk max + single rescale
            float mc = s[0];
            #pragma unroll
            for (int jj = 1; jj < 8; jj++) mc = fmaxf(mc, s[jj]);
            float m_new = fmaxf(m, mc);
            float corr = __expf(m - m_new);   // m=-inf only before first valid key -> corr=0
            l *= corr;
            #pragma unroll
            for (int i = 0; i < 16; i++) {
                acc[i].x *= corr; acc[i].y *= corr;
                acc[i].z *= corr; acc[i].w *= corr;
            }
            // 3) accumulate p_j * V_j
            #pragma unroll
            for (int jj = 0; jj < 8; jj++) {
                const int j = jc + jj;
                float p = __expf(s[jj] - m_new);   // masked -> exp(-inf)=0
                l += p;
                #pragma unroll
                for (int i = 0; i < 16; i++) {
                    float4 vv = *(const float4*)&Vs[j][i * 4];
                    acc[i].x = fmaf(p, vv.x, acc[i].x);
                    acc[i].y = fmaf(p, vv.y, acc[i].y);
                    acc[i].z = fmaf(p, vv.z, acc[i].z);
                    acc[i].w = fmaf(p, vv.w, acc[i].w);
                }
            }
            m = m_new;
        }
        __syncthreads();
    }

    const float inv = 1.f / l;
    float* yb = y + ((size_t)(b * Tn + qi)) * Cn + h * HDn;
    #pragma unroll
    for (int i = 0; i < 16; i++) {
        float4 o;
        o.x = acc[i].x * inv; o.y = acc[i].y * inv;
        o.z = acc[i].z * inv; o.w = acc[i].w * inv;
        *(float4*)(yb + i * 4) = o;
    }
}

// ---------------------------------------------------------------------------
// Launch
// ---------------------------------------------------------------------------
extern "C" void kernel_launch(void* const* d_in, const int* in_sizes, int n_in,
                              void* d_out, int out_size)
{
    const float* x      = (const float*)d_in[0];
    const float* w_attn = (const float*)d_in[1];
    const float* b_attn = (const float*)d_in[2];
    const float* w_proj = (const float*)d_in[3];
    const float* b_proj = (const float*)d_in[4];
    float* out = (float*)d_out;

    float* qkv_ptr = nullptr;
    float* y_ptr   = nullptr;
    cudaGetSymbolAddress((void**)&qkv_ptr, g_qkv);
    cudaGetSymbolAddress((void**)&y_ptr,   g_y);

    // 1) QKV projection: [4096,1024] @ [1024,3072] + b_attn
    {
        dim3 grid(QKV_N / BN, Mrows / BM);
        sgemm_bias<<<grid, 256>>>(x, w_attn, b_attn, qkv_ptr, Mrows, QKV_N, Cn);
    }
    // 2) Causal attention
    {
        dim3 grid(Tn / BQ, Hn, Bn);
        attn_kernel<<<grid, BQ>>>(qkv_ptr, y_ptr);
    }
    // 3) Output projection: [4096,1024] @ [1024,1024] + b_proj
    {
        dim3 grid(Cn / BN, Mrows / BM);
        sgemm_bias<<<grid, 256>>>(y_ptr, w_proj, b_proj, out, Mrows, Cn, Cn);
    }
}

// round 2
// speedup vs baseline: 1.8346x; 1.8346x over previous
#include <cuda_runtime.h>
#include <cuda_bf16.h>
#include <math.h>
#include <stdint.h>

// Problem constants
#define Bn  2
#define Tn  2048
#define Cn  1024
#define Hn  16
#define HDn 64
#define QKV_N (3*Cn)          // 3072
#define Mrows (Bn*Tn)         // 4096

// Scratch (allocation-free: __device__ globals)
__device__ float g_qkv[(size_t)Mrows * QKV_N];   // [B*T, 3C]  48 MB
__device__ float g_y[(size_t)Mrows * Cn];        // [B*T, C]   32 MB

// ---------------------------------------------------------------------------
// SGEMM: C[M,N] = A[M,K] @ W[K,N] + bias[N]  (unchanged from R0)
// ---------------------------------------------------------------------------
#define BM 128
#define BN 128
#define BK 8

__global__ __launch_bounds__(256)
void sgemm_bias(const float* __restrict__ A, const float* __restrict__ W,
                const float* __restrict__ bias, float* __restrict__ C,
                int M, int N, int K)
{
    __shared__ float As[BK][BM];
    __shared__ float Bs[BK][BN];

    const int tid = threadIdx.x;
    const int bm = blockIdx.y * BM;
    const int bn = blockIdx.x * BN;

    const int arow = tid >> 1;
    const int acol = (tid & 1) * 4;
    const int brow = tid >> 5;
    const int bcol = (tid & 31) * 4;

    const float* Aptr = A + (size_t)(bm + arow) * K + acol;
    const float* Wptr = W + (size_t)brow * N + bn + bcol;

    const int tx = tid & 15;
    const int ty = tid >> 4;
    const int mro = ty * 8;
    const int nco = tx * 8;

    float acc[8][8];
    #pragma unroll
    for (int i = 0; i < 8; i++)
        #pragma unroll
        for (int j = 0; j < 8; j++) acc[i][j] = 0.f;

    for (int k0 = 0; k0 < K; k0 += BK) {
        float4 av = *(const float4*)Aptr;  Aptr += BK;
        float4 wv = *(const float4*)Wptr;  Wptr += (size_t)BK * N;

        As[acol + 0][arow] = av.x;
        As[acol + 1][arow] = av.y;
        As[acol + 2][arow] = av.z;
        As[acol + 3][arow] = av.w;
        *(float4*)&Bs[brow][bcol] = wv;
        __syncthreads();

        #pragma unroll
        for (int kk = 0; kk < BK; kk++) {
            float a[8], b[8];
            *(float4*)&a[0] = *(const float4*)&As[kk][mro];
            *(float4*)&a[4] = *(const float4*)&As[kk][mro + 4];
            *(float4*)&b[0] = *(const float4*)&Bs[kk][nco];
            *(float4*)&b[4] = *(const float4*)&Bs[kk][nco + 4];
            #pragma unroll
            for (int i = 0; i < 8; i++)
                #pragma unroll
                for (int j = 0; j < 8; j++)
                    acc[i][j] = fmaf(a[i], b[j], acc[i][j]);
        }
        __syncthreads();
    }

    float bsv[8];
    *(float4*)&bsv[0] = *(const float4*)&bias[bn + nco];
    *(float4*)&bsv[4] = *(const float4*)&bias[bn + nco + 4];
    #pragma unroll
    for (int i = 0; i < 8; i++) {
        float* crow = C + (size_t)(bm + mro + i) * N + bn + nco;
        float4 o0, o1;
        o0.x = acc[i][0] + bsv[0]; o0.y = acc[i][1] + bsv[1];
        o0.z = acc[i][2] + bsv[2]; o0.w = acc[i][3] + bsv[3];
        o1.x = acc[i][4] + bsv[4]; o1.y = acc[i][5] + bsv[5];
        o1.z = acc[i][6] + bsv[6]; o1.w = acc[i][7] + bsv[7];
        *(float4*)&crow[0] = o0;
        *(float4*)&crow[4] = o1;
    }
}

// ---------------------------------------------------------------------------
// Tensor-core flash attention (tf32 mma.sync.m16n8k8), causal, HD=64.
// CTA: 128 threads (4 warps), BQ=64 queries (16 rows/warp), KV tiles of 64.
// Q-frags + O-accum + scores in registers; K/V in padded smem.
// ---------------------------------------------------------------------------
#define AT_BQ   64
#define AT_BKV  64
#define KPAD    66           // smem row stride (floats): <=2-way conflicts
#define SCALE   0.125f       // 1/sqrt(64)

__device__ __forceinline__ float tf32r(float x) {
    uint32_t u;
    asm("cvt.rna.tf32.f32 %0, %1;" : "=r"(u) : "f"(x));
    return __uint_as_float(u);
}

__device__ __forceinline__ void mma_tf32(float d[4], const uint32_t a[4],
                                         uint32_t b0, uint32_t b1) {
    asm volatile(
        "mma.sync.aligned.m16n8k8.row.col.f32.tf32.tf32.f32 "
        "{%0,%1,%2,%3}, {%4,%5,%6,%7}, {%8,%9}, {%0,%1,%2,%3};"
        : "+f"(d[0]), "+f"(d[1]), "+f"(d[2]), "+f"(d[3])
        : "r"(a[0]), "r"(a[1]), "r"(a[2]), "r"(a[3]), "r"(b0), "r"(b1));
}

__global__ __launch_bounds__(128)
void attn_tc(const float* __restrict__ qkv, float* __restrict__ y)
{
    __shared__ float Ks[AT_BKV][KPAD];
    __shared__ float Vs[AT_BKV][KPAD];

    const int b = blockIdx.z, h = blockIdx.y;
    const int qtile = gridDim.x - 1 - blockIdx.x;   // heavy tiles first
    const int q0 = qtile * AT_BQ;
    const int tid  = threadIdx.x;
    const int warp = tid >> 5;
    const int lane = tid & 31;
    const int g  = lane >> 2;       // group (row) id 0..7
    const int tg = lane & 3;        // thread in group 0..3

    // ---- stage Q tile into Ks (as tf32 bits), then load A-frags ----
    {
        const float* qg = qkv + ((size_t)(b * Tn + q0)) * QKV_N + h * HDn;
        #pragma unroll
        for (int it = 0; it < 8; it++) {
            int f = it * 128 + tid;
            int r = f >> 4, c = (f & 15) << 2;
            float4 v = *(const float4*)(qg + (size_t)r * QKV_N + c);
            Ks[r][c + 0] = tf32r(v.x);
            Ks[r][c + 1] = tf32r(v.y);
            Ks[r][c + 2] = tf32r(v.z);
            Ks[r][c + 3] = tf32r(v.w);
        }
    }
    __syncthreads();

    uint32_t Aq[8][4];   // Q A-frags for 8 k-steps
    {
        const int r0 = warp * 16 + g;
        #pragma unroll
        for (int k = 0; k < 8; k++) {
            Aq[k][0] = __float_as_uint(Ks[r0    ][k * 8 + tg    ]);
            Aq[k][1] = __float_as_uint(Ks[r0 + 8][k * 8 + tg    ]);
            Aq[k][2] = __float_as_uint(Ks[r0    ][k * 8 + tg + 4]);
            Aq[k][3] = __float_as_uint(Ks[r0 + 8][k * 8 + tg + 4]);
        }
    }
    __syncthreads();

    float O[8][4];
    #pragma unroll
    for (int nt = 0; nt < 8; nt++)
        #pragma unroll
        for (int i = 0; i < 4; i++) O[nt][i] = 0.f;

    float m0 = -INFINITY, m1 = -INFINITY;
    float l0 = 0.f, l1 = 0.f;

    const int qi0 = q0 + warp * 16 + g;
    const int qi1 = qi0 + 8;

    for (int kt = 0; kt <= q0; kt += AT_BKV) {
        // ---- stage K and V tiles (tf32 bits) ----
        {
            const float* kg = qkv + ((size_t)(b * Tn + kt)) * QKV_N +     Cn + h * HDn;
            const float* vg = qkv + ((size_t)(b * Tn + kt)) * QKV_N + 2 * Cn + h * HDn;
            #pragma unroll
            for (int it = 0; it < 8; it++) {
                int f = it * 128 + tid;
                int r = f >> 4, c = (f & 15) << 2;
                float4 kv4 = *(const float4*)(kg + (size_t)r * QKV_N + c);
                float4 vv4 = *(const float4*)(vg + (size_t)r * QKV_N + c);
                Ks[r][c + 0] = tf32r(kv4.x);
                Ks[r][c + 1] = tf32r(kv4.y);
                Ks[r][c + 2] = tf32r(kv4.z);
                Ks[r][c + 3] = tf32r(kv4.w);
                Vs[r][c + 0] = tf32r(vv4.x);
                Vs[r][c + 1] = tf32r(vv4.y);
                Vs[r][c + 2] = tf32r(vv4.z);
                Vs[r][c + 3] = tf32r(vv4.w);
            }
        }
        __syncthreads();

        // ---- S = Q @ K^T (per-warp 16x64), scale + causal mask ----
        float S[8][4];
        #pragma unroll
        for (int nt = 0; nt < 8; nt++) {
            S[nt][0] = S[nt][1] = S[nt][2] = S[nt][3] = 0.f;
            #pragma unroll
            for (int k = 0; k < 8; k++) {
                uint32_t b0 = __float_as_uint(Ks[nt * 8 + g][k * 8 + tg    ]);
                uint32_t b1 = __float_as_uint(Ks[nt * 8 + g][k * 8 + tg + 4]);
                mma_tf32(S[nt], Aq[k], b0, b1);
            }
        }

        const bool diag = (kt == q0);
        #pragma unroll
        for (int nt = 0; nt < 8; nt++) {
            int j0 = kt + nt * 8 + 2 * tg;
            int j1 = j0 + 1;
            S[nt][0] *= SCALE; S[nt][1] *= SCALE;
            S[nt][2] *= SCALE; S[nt][3] *= SCALE;
            if (diag) {
                if (j0 > qi0) S[nt][0] = -INFINITY;
                if (j1 > qi0) S[nt][1] = -INFINITY;
                if (j0 > qi1) S[nt][2] = -INFINITY;
                if (j1 > qi1) S[nt][3] = -INFINITY;
            }
        }

        // ---- online softmax (rows qi0, qi1) ----
        float mc0 = -INFINITY, mc1 = -INFINITY;
        #pragma unroll
        for (int nt = 0; nt < 8; nt++) {
            mc0 = fmaxf(mc0, fmaxf(S[nt][0], S[nt][1]));
            mc1 = fmaxf(mc1, fmaxf(S[nt][2], S[nt][3]));
        }
        mc0 = fmaxf(mc0, __shfl_xor_sync(0xffffffffu, mc0, 1));
        mc0 = fmaxf(mc0, __shfl_xor_sync(0xffffffffu, mc0, 2));
        mc1 = fmaxf(mc1, __shfl_xor_sync(0xffffffffu, mc1, 1));
        mc1 = fmaxf(mc1, __shfl_xor_sync(0xffffffffu, mc1, 2));

        float mn0 = fmaxf(m0, mc0);
        float mn1 = fmaxf(m1, mc1);
        float corr0 = __expf(m0 - mn0);
        float corr1 = __expf(m1 - mn1);
        m0 = mn0; m1 = mn1;

        float ps0 = 0.f, ps1 = 0.f;
        #pragma unroll
        for (int nt = 0; nt < 8; nt++) {
            S[nt][0] = __expf(S[nt][0] - mn0);
            S[nt][1] = __expf(S[nt][1] - mn0);
            S[nt][2] = __expf(S[nt][2] - mn1);
            S[nt][3] = __expf(S[nt][3] - mn1);
            ps0 += S[nt][0] + S[nt][1];
            ps1 += S[nt][2] + S[nt][3];
        }
        ps0 += __shfl_xor_sync(0xffffffffu, ps0, 1);
        ps0 += __shfl_xor_sync(0xffffffffu, ps0, 2);
        ps1 += __shfl_xor_sync(0xffffffffu, ps1, 1);
        ps1 += __shfl_xor_sync(0xffffffffu, ps1, 2);
        l0 = l0 * corr0 + ps0;
        l1 = l1 * corr1 + ps1;

        #pragma unroll
        for (int nt = 0; nt < 8; nt++) {
            O[nt][0] *= corr0; O[nt][1] *= corr0;
            O[nt][2] *= corr1; O[nt][3] *= corr1;
        }

        // ---- O += P @ V ----
        const int src_lo = (lane & ~3) | (tg >> 1);
        const int src_hi = src_lo + 2;
        const bool odd = (tg & 1);
        #pragma unroll
        for (int kk = 0; kk < 8; kk++) {
            // convert P tile kk from C-frag layout to A-frag layout via shfl
            float p0 = S[kk][0], p1 = S[kk][1], p2 = S[kk][2], p3 = S[kk][3];
            float u, v;
            uint32_t Ap[4];
            u = __shfl_sync(0xffffffffu, p0, src_lo);
            v = __shfl_sync(0xffffffffu, p1, src_lo);
            Ap[0] = __float_as_uint(tf32r(odd ? v : u));
            u = __shfl_sync(0xffffffffu, p2, src_lo);
            v = __shfl_sync(0xffffffffu, p3, src_lo);
            Ap[1] = __float_as_uint(tf32r(odd ? v : u));
            u = __shfl_sync(0xffffffffu, p0, src_hi);
            v = __shfl_sync(0xffffffffu, p1, src_hi);
            Ap[2] = __float_as_uint(tf32r(odd ? v : u));
            u = __shfl_sync(0xffffffffu, p2, src_hi);
            v = __shfl_sync(0xffffffffu, p3, src_hi);
            Ap[3] = __float_as_uint(tf32r(odd ? v : u));

            #pragma unroll
            for (int dd = 0; dd < 8; dd++) {
                uint32_t b0 = __float_as_uint(Vs[kk * 8 + tg    ][dd * 8 + g]);
                uint32_t b1 = __float_as_uint(Vs[kk * 8 + tg + 4][dd * 8 + g]);
                mma_tf32(O[dd], Ap, b0, b1);
            }
        }
        __syncthreads();
    }

    // ---- finalize: divide by l, store ----
    const float inv0 = 1.f / l0;
    const float inv1 = 1.f / l1;
    float* y0 = y + ((size_t)(b * Tn + qi0)) * Cn + h * HDn;
    float* y1 = y + ((size_t)(b * Tn + qi1)) * Cn + h * HDn;
    #pragma unroll
    for (int nt = 0; nt < 8; nt++) {
        int c = nt * 8 + 2 * tg;
        float2 o0 = make_float2(O[nt][0] * inv0, O[nt][1] * inv0);
        float2 o1 = make_float2(O[nt][2] * inv1, O[nt][3] * inv1);
        *(float2*)(y0 + c) = o0;
        *(float2*)(y1 + c) = o1;
    }
}

// ---------------------------------------------------------------------------
// Launch
// ---------------------------------------------------------------------------
extern "C" void kernel_launch(void* const* d_in, const int* in_sizes, int n_in,
                              void* d_out, int out_size)
{
    const float* x      = (const float*)d_in[0];
    const float* w_attn = (const float*)d_in[1];
    const float* b_attn = (const float*)d_in[2];
    const float* w_proj = (const float*)d_in[3];
    const float* b_proj = (const float*)d_in[4];
    float* out = (float*)d_out;

    float* qkv_ptr = nullptr;
    float* y_ptr   = nullptr;
    cudaGetSymbolAddress((void**)&qkv_ptr, g_qkv);
    cudaGetSymbolAddress((void**)&y_ptr,   g_y);

    // 1) QKV projection: [4096,1024] @ [1024,3072] + b_attn
    {
        dim3 grid(QKV_N / BN, Mrows / BM);
        sgemm_bias<<<grid, 256>>>(x, w_attn, b_attn, qkv_ptr, Mrows, QKV_N, Cn);
    }
    // 2) Causal attention (tensor cores, tf32)
    {
        dim3 grid(Tn / AT_BQ, Hn, Bn);
        attn_tc<<<grid, 128>>>(qkv_ptr, y_ptr);
    }
    // 3) Output projection: [4096,1024] @ [1024,1024] + b_proj
    {
        dim3 grid(Cn / BN, Mrows / BM);
        sgemm_bias<<<grid, 256>>>(y_ptr, w_proj, b_proj, out, Mrows, Cn, Cn);
    }
}

// round 3
// speedup vs baseline: 2.8177x; 1.5359x over previous
#include <cuda_runtime.h>
#include <cuda_bf16.h>
#include <math.h>
#include <stdint.h>

// Problem constants
#define Bn  2
#define Tn  2048
#define Cn  1024
#define Hn  16
#define HDn 64
#define QKV_N (3*Cn)          // 3072
#define Mrows (Bn*Tn)         // 4096

// Scratch (allocation-free: __device__ globals)
__device__ float g_qkv[(size_t)Mrows * QKV_N];   // [B*T, 3C]  48 MB
__device__ float g_y[(size_t)Mrows * Cn];        // [B*T, C]   32 MB

// ===========================================================================
// Tensor-core GEMM with bf16x3 split (fp32-accurate):
// C[M,N] = A[M,K] @ W[K,N] + bias[N]
// CTA tile 128x128, K-chunk 32, 8 warps (warp tile 32x64), mma.m16n8k16.bf16
// ===========================================================================
#define GBM 128
#define GBN 128
#define GBK 32
#define APAD 40    // A smem row stride (bf16) -> 20 words, conflict-free ldmatrix
#define BPAD 136   // B smem row stride (bf16) -> 68 words, conflict-free ldmatrix

__device__ __forceinline__ void ldsm4(uint32_t r[4], uint32_t addr) {
    asm volatile("ldmatrix.sync.aligned.m8n8.x4.shared.b16 {%0,%1,%2,%3}, [%4];"
                 : "=r"(r[0]), "=r"(r[1]), "=r"(r[2]), "=r"(r[3]) : "r"(addr));
}
__device__ __forceinline__ void ldsm4t(uint32_t r[4], uint32_t addr) {
    asm volatile("ldmatrix.sync.aligned.m8n8.x4.trans.shared.b16 {%0,%1,%2,%3}, [%4];"
                 : "=r"(r[0]), "=r"(r[1]), "=r"(r[2]), "=r"(r[3]) : "r"(addr));
}
__device__ __forceinline__ void mma_bf16(float d[4], const uint32_t a[4],
                                         uint32_t b0, uint32_t b1) {
    asm volatile(
        "mma.sync.aligned.m16n8k16.row.col.f32.bf16.bf16.f32 "
        "{%0,%1,%2,%3}, {%4,%5,%6,%7}, {%8,%9}, {%0,%1,%2,%3};"
        : "+f"(d[0]), "+f"(d[1]), "+f"(d[2]), "+f"(d[3])
        : "r"(a[0]), "r"(a[1]), "r"(a[2]), "r"(a[3]), "r"(b0), "r"(b1));
}

// split x into bf16 hi + lo (lo = bf16(x - hi)); packs pairs for smem stores
__device__ __forceinline__ void split4(float4 v, __nv_bfloat162 hi[2], __nv_bfloat162 lo[2]) {
    __nv_bfloat16 hx = __float2bfloat16(v.x), hy = __float2bfloat16(v.y);
    __nv_bfloat16 hz = __float2bfloat16(v.z), hw = __float2bfloat16(v.w);
    hi[0] = __nv_bfloat162(hx, hy);
    hi[1] = __nv_bfloat162(hz, hw);
    lo[0] = __nv_bfloat162(__float2bfloat16(v.x - __bfloat162float(hx)),
                           __float2bfloat16(v.y - __bfloat162float(hy)));
    lo[1] = __nv_bfloat162(__float2bfloat16(v.z - __bfloat162float(hz)),
                           __float2bfloat16(v.w - __bfloat162float(hw)));
}

__global__ __launch_bounds__(256)
void hgemm_bias(const float* __restrict__ A, const float* __restrict__ W,
                const float* __restrict__ bias, float* __restrict__ C,
                int M, int N, int K)
{
    __shared__ __nv_bfloat16 Ahi[GBM][APAD];
    __shared__ __nv_bfloat16 Alo[GBM][APAD];
    __shared__ __nv_bfloat16 Bhi[GBK][BPAD];
    __shared__ __nv_bfloat16 Blo[GBK][BPAD];

    const int tid  = threadIdx.x;
    const int warp = tid >> 5;
    const int lane = tid & 31;
    const int g  = lane >> 2;
    const int tg = lane & 3;

    const int bm = blockIdx.y * GBM;
    const int bn = blockIdx.x * GBN;
    const int warp_m = (warp >> 1) * 32;   // 0,32,64,96
    const int warp_n = (warp & 1) * 64;    // 0,64

    // gmem staging assignment
    const int arow  = tid >> 1;            // 0..127
    const int acol0 = (tid & 1) * 16;      // 0 or 16
    const int brow  = tid >> 3;            // 0..31
    const int bcol0 = (tid & 7) * 16;      // 0..112

    const float* Ag = A + (size_t)(bm + arow) * K + acol0;
    const float* Wg = W + (size_t)brow * N + bn + bcol0;

    // ldmatrix source addresses (fixed per thread, offset by mt/ks/npair)
    const int a_r = lane & 15;
    const int a_c = (lane >> 4) * 8;
    uint32_t AhiBase = (uint32_t)__cvta_generic_to_shared(&Ahi[0][0]);
    uint32_t AloBase = (uint32_t)__cvta_generic_to_shared(&Alo[0][0]);
    uint32_t BhiBase = (uint32_t)__cvta_generic_to_shared(&Bhi[0][0]);
    uint32_t BloBase = (uint32_t)__cvta_generic_to_shared(&Blo[0][0]);

    float4 ra[4], rb[4];
    #pragma unroll
    for (int i = 0; i < 4; i++) {
        ra[i] = *(const float4*)(Ag + 4 * i);
        rb[i] = *(const float4*)(Wg + 4 * i);
    }

    float acc[2][8][4];
    #pragma unroll
    for (int mt = 0; mt < 2; mt++)
        #pragma unroll
        for (int nt = 0; nt < 8; nt++)
            #pragma unroll
            for (int i = 0; i < 4; i++) acc[mt][nt][i] = 0.f;

    for (int k0 = 0; k0 < K; k0 += GBK) {
        // ---- convert staged regs to bf16 hi/lo and store to smem ----
        #pragma unroll
        for (int i = 0; i < 4; i++) {
            __nv_bfloat162 h[2], l[2];
            split4(ra[i], h, l);
            *(__nv_bfloat162*)&Ahi[arow][acol0 + 4 * i]     = h[0];
            *(__nv_bfloat162*)&Ahi[arow][acol0 + 4 * i + 2] = h[1];
            *(__nv_bfloat162*)&Alo[arow][acol0 + 4 * i]     = l[0];
            *(__nv_bfloat162*)&Alo[arow][acol0 + 4 * i + 2] = l[1];
            split4(rb[i], h, l);
            *(__nv_bfloat162*)&Bhi[brow][bcol0 + 4 * i]     = h[0];
            *(__nv_bfloat162*)&Bhi[brow][bcol0 + 4 * i + 2] = h[1];
            *(__nv_bfloat162*)&Blo[brow][bcol0 + 4 * i]     = l[0];
            *(__nv_bfloat162*)&Blo[brow][bcol0 + 4 * i + 2] = l[1];
        }
        __syncthreads();

        // ---- prefetch next gmem tile ----
        if (k0 + GBK < K) {
            Ag += GBK;
            Wg += (size_t)GBK * N;
            #pragma unroll
            for (int i = 0; i < 4; i++) {
                ra[i] = *(const float4*)(Ag + 4 * i);
                rb[i] = *(const float4*)(Wg + 4 * i);
            }
        }

        // ---- compute: 2 k16 steps ----
        #pragma unroll
        for (int ks = 0; ks < 2; ks++) {
            const int kk = ks * 16;
            uint32_t ah[2][4], al[2][4];
            #pragma unroll
            for (int mt = 0; mt < 2; mt++) {
                uint32_t off = (uint32_t)((warp_m + mt * 16 + a_r) * APAD + kk + a_c) * 2;
                ldsm4(ah[mt], AhiBase + off);
                ldsm4(al[mt], AloBase + off);
            }
            #pragma unroll
            for (int np = 0; np < 4; np++) {
                uint32_t bh[4], bl[4];
                uint32_t off = (uint32_t)((kk + a_r) * BPAD + warp_n + np * 16 + a_c) * 2;
                ldsm4t(bh, BhiBase + off);
                ldsm4t(bl, BloBase + off);
                #pragma unroll
                for (int half = 0; half < 2; half++) {
                    const int nt = np * 2 + half;
                    uint32_t b0h = bh[half * 2], b1h = bh[half * 2 + 1];
                    uint32_t b0l = bl[half * 2], b1l = bl[half * 2 + 1];
                    #pragma unroll
                    for (int mt = 0; mt < 2; mt++) {
                        mma_bf16(acc[mt][nt], ah[mt], b0h, b1h);   // hi*hi
                        mma_bf16(acc[mt][nt], ah[mt], b0l, b1l);   // hi*lo
                        mma_bf16(acc[mt][nt], al[mt], b0h, b1h);   // lo*hi
                    }
                }
            }
        }
        __syncthreads();
    }

    // ---- epilogue: add bias, store ----
    #pragma unroll
    for (int nt = 0; nt < 8; nt++) {
        const int col = bn + warp_n + nt * 8 + 2 * tg;
        const float2 bs = *(const float2*)&bias[col];
        #pragma unroll
        for (int mt = 0; mt < 2; mt++) {
            const int row0 = bm + warp_m + mt * 16 + g;
            float2 o0 = make_float2(acc[mt][nt][0] + bs.x, acc[mt][nt][1] + bs.y);
            float2 o1 = make_float2(acc[mt][nt][2] + bs.x, acc[mt][nt][3] + bs.y);
            *(float2*)&C[(size_t)row0 * N + col]       = o0;
            *(float2*)&C[(size_t)(row0 + 8) * N + col] = o1;
        }
    }
}

// ---------------------------------------------------------------------------
// Tensor-core flash attention (tf32 mma.sync.m16n8k8), causal, HD=64.
// (unchanged from R1)
// ---------------------------------------------------------------------------
#define AT_BQ   64
#define AT_BKV  64
#define KPAD    66
#define SCALE   0.125f

__device__ __forceinline__ float tf32r(float x) {
    uint32_t u;
    asm("cvt.rna.tf32.f32 %0, %1;" : "=r"(u) : "f"(x));
    return __uint_as_float(u);
}

__device__ __forceinline__ void mma_tf32(float d[4], const uint32_t a[4],
                                         uint32_t b0, uint32_t b1) {
    asm volatile(
        "mma.sync.aligned.m16n8k8.row.col.f32.tf32.tf32.f32 "
        "{%0,%1,%2,%3}, {%4,%5,%6,%7}, {%8,%9}, {%0,%1,%2,%3};"
        : "+f"(d[0]), "+f"(d[1]), "+f"(d[2]), "+f"(d[3])
        : "r"(a[0]), "r"(a[1]), "r"(a[2]), "r"(a[3]), "r"(b0), "r"(b1));
}

__global__ __launch_bounds__(128)
void attn_tc(const float* __restrict__ qkv, float* __restrict__ y)
{
    __shared__ float Ks[AT_BKV][KPAD];
    __shared__ float Vs[AT_BKV][KPAD];

    const int b = blockIdx.z, h = blockIdx.y;
    const int qtile = gridDim.x - 1 - blockIdx.x;
    const int q0 = qtile * AT_BQ;
    const int tid  = threadIdx.x;
    const int warp = tid >> 5;
    const int lane = tid & 31;
    const int g  = lane >> 2;
    const int tg = lane & 3;

    {
        const float* qg = qkv + ((size_t)(b * Tn + q0)) * QKV_N + h * HDn;
        #pragma unroll
        for (int it = 0; it < 8; it++) {
            int f = it * 128 + tid;
            int r = f >> 4, c = (f & 15) << 2;
            float4 v = *(const float4*)(qg + (size_t)r * QKV_N + c);
            Ks[r][c + 0] = tf32r(v.x);
            Ks[r][c + 1] = tf32r(v.y);
            Ks[r][c + 2] = tf32r(v.z);
            Ks[r][c + 3] = tf32r(v.w);
        }
    }
    __syncthreads();

    uint32_t Aq[8][4];
    {
        const int r0 = warp * 16 + g;
        #pragma unroll
        for (int k = 0; k < 8; k++) {
            Aq[k][0] = __float_as_uint(Ks[r0    ][k * 8 + tg    ]);
            Aq[k][1] = __float_as_uint(Ks[r0 + 8][k * 8 + tg    ]);
            Aq[k][2] = __float_as_uint(Ks[r0    ][k * 8 + tg + 4]);
            Aq[k][3] = __float_as_uint(Ks[r0 + 8][k * 8 + tg + 4]);
        }
    }
    __syncthreads();

    float O[8][4];
    #pragma unroll
    for (int nt = 0; nt < 8; nt++)
        #pragma unroll
        for (int i = 0; i < 4; i++) O[nt][i] = 0.f;

    float m0 = -INFINITY, m1 = -INFINITY;
    float l0 = 0.f, l1 = 0.f;

    const int qi0 = q0 + warp * 16 + g;
    const int qi1 = qi0 + 8;

    for (int kt = 0; kt <= q0; kt += AT_BKV) {
        {
            const float* kg = qkv + ((size_t)(b * Tn + kt)) * QKV_N +     Cn + h * HDn;
            const float* vg = qkv + ((size_t)(b * Tn + kt)) * QKV_N + 2 * Cn + h * HDn;
            #pragma unroll
            for (int it = 0; it < 8; it++) {
                int f = it * 128 + tid;
                int r = f >> 4, c = (f & 15) << 2;
                float4 kv4 = *(const float4*)(kg + (size_t)r * QKV_N + c);
                float4 vv4 = *(const float4*)(vg + (size_t)r * QKV_N + c);
                Ks[r][c + 0] = tf32r(kv4.x);
                Ks[r][c + 1] = tf32r(kv4.y);
                Ks[r][c + 2] = tf32r(kv4.z);
                Ks[r][c + 3] = tf32r(kv4.w);
                Vs[r][c + 0] = tf32r(vv4.x);
                Vs[r][c + 1] = tf32r(vv4.y);
                Vs[r][c + 2] = tf32r(vv4.z);
                Vs[r][c + 3] = tf32r(vv4.w);
            }
        }
        __syncthreads();

        float S[8][4];
        #pragma unroll
        for (int nt = 0; nt < 8; nt++) {
            S[nt][0] = S[nt][1] = S[nt][2] = S[nt][3] = 0.f;
            #pragma unroll
            for (int k = 0; k < 8; k++) {
                uint32_t b0 = __float_as_uint(Ks[nt * 8 + g][k * 8 + tg    ]);
                uint32_t b1 = __float_as_uint(Ks[nt * 8 + g][k * 8 + tg + 4]);
                mma_tf32(S[nt], Aq[k], b0, b1);
            }
        }

        const bool diag = (kt == q0);
        #pragma unroll
        for (int nt = 0; nt < 8; nt++) {
            int j0 = kt + nt * 8 + 2 * tg;
            int j1 = j0 + 1;
            S[nt][0] *= SCALE; S[nt][1] *= SCALE;
            S[nt][2] *= SCALE; S[nt][3] *= SCALE;
            if (diag) {
                if (j0 > qi0) S[nt][0] = -INFINITY;
                if (j1 > qi0) S[nt][1] = -INFINITY;
                if (j0 > qi1) S[nt][2] = -INFINITY;
                if (j1 > qi1) S[nt][3] = -INFINITY;
            }
        }

        float mc0 = -INFINITY, mc1 = -INFINITY;
        #pragma unroll
        for (int nt = 0; nt < 8; nt++) {
            mc0 = fmaxf(mc0, fmaxf(S[nt][0], S[nt][1]));
            mc1 = fmaxf(mc1, fmaxf(S[nt][2], S[nt][3]));
        }
        mc0 = fmaxf(mc0, __shfl_xor_sync(0xffffffffu, mc0, 1));
        mc0 = fmaxf(mc0, __shfl_xor_sync(0xffffffffu, mc0, 2));
        mc1 = fmaxf(mc1, __shfl_xor_sync(0xffffffffu, mc1, 1));
        mc1 = fmaxf(mc1, __shfl_xor_sync(0xffffffffu, mc1, 2));

        float mn0 = fmaxf(m0, mc0);
        float mn1 = fmaxf(m1, mc1);
        float corr0 = __expf(m0 - mn0);
        float corr1 = __expf(m1 - mn1);
        m0 = mn0; m1 = mn1;

        float ps0 = 0.f, ps1 = 0.f;
        #pragma unroll
        for (int nt = 0; nt < 8; nt++) {
            S[nt][0] = __expf(S[nt][0] - mn0);
            S[nt][1] = __expf(S[nt][1] - mn0);
            S[nt][2] = __expf(S[nt][2] - mn1);
            S[nt][3] = __expf(S[nt][3] - mn1);
            ps0 += S[nt][0] + S[nt][1];
            ps1 += S[nt][2] + S[nt][3];
        }
        ps0 += __shfl_xor_sync(0xffffffffu, ps0, 1);
        ps0 += __shfl_xor_sync(0xffffffffu, ps0, 2);
        ps1 += __shfl_xor_sync(0xffffffffu, ps1, 1);
        ps1 += __shfl_xor_sync(0xffffffffu, ps1, 2);
        l0 = l0 * corr0 + ps0;
        l1 = l1 * corr1 + ps1;

        #pragma unroll
        for (int nt = 0; nt < 8; nt++) {
            O[nt][0] *= corr0; O[nt][1] *= corr0;
            O[nt][2] *= corr1; O[nt][3] *= corr1;
        }

        const int src_lo = (lane & ~3) | (tg >> 1);
        const int src_hi = src_lo + 2;
        const bool odd = (tg & 1);
        #pragma unroll
        for (int kk = 0; kk < 8; kk++) {
            float p0 = S[kk][0], p1 = S[kk][1], p2 = S[kk][2], p3 = S[kk][3];
            float u, v;
            uint32_t Ap[4];
            u = __shfl_sync(0xffffffffu, p0, src_lo);
            v = __shfl_sync(0xffffffffu, p1, src_lo);
            Ap[0] = __float_as_uint(tf32r(odd ? v : u));
            u = __shfl_sync(0xffffffffu, p2, src_lo);
            v = __shfl_sync(0xffffffffu, p3, src_lo);
            Ap[1] = __float_as_uint(tf32r(odd ? v : u));
            u = __shfl_sync(0xffffffffu, p0, src_hi);
            v = __shfl_sync(0xffffffffu, p1, src_hi);
            Ap[2] = __float_as_uint(tf32r(odd ? v : u));
            u = __shfl_sync(0xffffffffu, p2, src_hi);
            v = __shfl_sync(0xffffffffu, p3, src_hi);
            Ap[3] = __float_as_uint(tf32r(odd ? v : u));

            #pragma unroll
            for (int dd = 0; dd < 8; dd++) {
                uint32_t b0 = __float_as_uint(Vs[kk * 8 + tg    ][dd * 8 + g]);
                uint32_t b1 = __float_as_uint(Vs[kk * 8 + tg + 4][dd * 8 + g]);
                mma_tf32(O[dd], Ap, b0, b1);
            }
        }
        __syncthreads();
    }

    const float inv0 = 1.f / l0;
    const float inv1 = 1.f / l1;
    float* y0 = y + ((size_t)(b * Tn + qi0)) * Cn + h * HDn;
    float* y1 = y + ((size_t)(b * Tn + qi1)) * Cn + h * HDn;
    #pragma unroll
    for (int nt = 0; nt < 8; nt++) {
        int c = nt * 8 + 2 * tg;
        float2 o0 = make_float2(O[nt][0] * inv0, O[nt][1] * inv0);
        float2 o1 = make_float2(O[nt][2] * inv1, O[nt][3] * inv1);
        *(float2*)(y0 + c) = o0;
        *(float2*)(y1 + c) = o1;
    }
}

// ---------------------------------------------------------------------------
// Launch
// ---------------------------------------------------------------------------
extern "C" void kernel_launch(void* const* d_in, const int* in_sizes, int n_in,
                              void* d_out, int out_size)
{
    const float* x      = (const float*)d_in[0];
    const float* w_attn = (const float*)d_in[1];
    const float* b_attn = (const float*)d_in[2];
    const float* w_proj = (const float*)d_in[3];
    const float* b_proj = (const float*)d_in[4];
    float* out = (float*)d_out;

    float* qkv_ptr = nullptr;
    float* y_ptr   = nullptr;
    cudaGetSymbolAddress((void**)&qkv_ptr, g_qkv);
    cudaGetSymbolAddress((void**)&y_ptr,   g_y);

    // 1) QKV projection: [4096,1024] @ [1024,3072] + b_attn  (tensor cores)
    {
        dim3 grid(QKV_N / GBN, Mrows / GBM);
        hgemm_bias<<<grid, 256>>>(x, w_attn, b_attn, qkv_ptr, Mrows, QKV_N, Cn);
    }
    // 2) Causal attention (tensor cores, tf32)
    {
        dim3 grid(Tn / AT_BQ, Hn, Bn);
        attn_tc<<<grid, 128>>>(qkv_ptr, y_ptr);
    }
    // 3) Output projection: [4096,1024] @ [1024,1024] + b_proj  (tensor cores)
    {
        dim3 grid(Cn / GBN, Mrows / GBM);
        hgemm_bias<<<grid, 256>>>(y_ptr, w_proj, b_proj, out, Mrows, Cn, Cn);
    }
}

// round 4
// speedup vs baseline: 3.9522x; 1.4026x over previous
#include <cuda_runtime.h>
#include <cuda_bf16.h>
#include <math.h>
#include <stdint.h>

// Problem constants
#define Bn  2
#define Tn  2048
#define Cn  1024
#define Hn  16
#define HDn 64
#define QKV_N (3*Cn)          // 3072
#define Mrows (Bn*Tn)         // 4096

// Scratch (allocation-free: __device__ globals)
__device__ float g_qkv[(size_t)Mrows * QKV_N];              // 48 MB fp32
__device__ __nv_bfloat16 g_xhi[(size_t)Mrows * Cn];
__device__ __nv_bfloat16 g_xlo[(size_t)Mrows * Cn];
__device__ __nv_bfloat16 g_wahi[(size_t)Cn * QKV_N];
__device__ __nv_bfloat16 g_walo[(size_t)Cn * QKV_N];
__device__ __nv_bfloat16 g_wphi[(size_t)Cn * Cn];
__device__ __nv_bfloat16 g_wplo[(size_t)Cn * Cn];
__device__ __nv_bfloat16 g_yhi[(size_t)Mrows * Cn];
__device__ __nv_bfloat16 g_ylo[(size_t)Mrows * Cn];

// ===========================================================================
// fp32 -> bf16 hi/lo split (elementwise, vectorized)
// ===========================================================================
__global__ __launch_bounds__(256)
void split_kernel(const float* __restrict__ src, __nv_bfloat16* __restrict__ hi,
                  __nv_bfloat16* __restrict__ lo, int n4)
{
    int i = blockIdx.x * blockDim.x + threadIdx.x;
    if (i >= n4) return;
    float4 v = ((const float4*)src)[i];
    __nv_bfloat16 hx = __float2bfloat16(v.x), hy = __float2bfloat16(v.y);
    __nv_bfloat16 hz = __float2bfloat16(v.z), hw = __float2bfloat16(v.w);
    ((__nv_bfloat162*)hi)[2 * i]     = __nv_bfloat162(hx, hy);
    ((__nv_bfloat162*)hi)[2 * i + 1] = __nv_bfloat162(hz, hw);
    ((__nv_bfloat162*)lo)[2 * i] = __nv_bfloat162(
        __float2bfloat16(v.x - __bfloat162float(hx)),
        __float2bfloat16(v.y - __bfloat162float(hy)));
    ((__nv_bfloat162*)lo)[2 * i + 1] = __nv_bfloat162(
        __float2bfloat16(v.z - __bfloat162float(hz)),
        __float2bfloat16(v.w - __bfloat162float(hw)));
}

// ===========================================================================
// Pipelined bf16 split GEMM: C = (Ahi+Alo) @ (Bhi+Blo) + bias  (3-pass MMA)
// CTA 128x128, GBK=32, cp.async double-buffer, 8 warps (warp tile 32x64)
// ===========================================================================
#define GBM 128
#define GBN 128
#define GBK 32
#define ASTR 40     // A smem row stride (bf16)
#define BSTR 136    // B smem row stride (bf16)
#define OFF_AHI 0
#define OFF_ALO 10240
#define OFF_BHI 20480
#define OFF_BLO 29184
#define STAGE_BYTES 37888
#define GEMM_SMEM (2*STAGE_BYTES)

__device__ __forceinline__ void cpasync16(uint32_t dst, const void* src) {
    asm volatile("cp.async.cg.shared.global [%0], [%1], 16;" :: "r"(dst), "l"(src));
}
__device__ __forceinline__ void ldsm4(uint32_t r[4], uint32_t addr) {
    asm volatile("ldmatrix.sync.aligned.m8n8.x4.shared.b16 {%0,%1,%2,%3}, [%4];"
                 : "=r"(r[0]), "=r"(r[1]), "=r"(r[2]), "=r"(r[3]) : "r"(addr));
}
__device__ __forceinline__ void ldsm4t(uint32_t r[4], uint32_t addr) {
    asm volatile("ldmatrix.sync.aligned.m8n8.x4.trans.shared.b16 {%0,%1,%2,%3}, [%4];"
                 : "=r"(r[0]), "=r"(r[1]), "=r"(r[2]), "=r"(r[3]) : "r"(addr));
}
__device__ __forceinline__ void mma_bf16(float d[4], const uint32_t a[4],
                                         uint32_t b0, uint32_t b1) {
    asm volatile(
        "mma.sync.aligned.m16n8k16.row.col.f32.bf16.bf16.f32 "
        "{%0,%1,%2,%3}, {%4,%5,%6,%7}, {%8,%9}, {%0,%1,%2,%3};"
        : "+f"(d[0]), "+f"(d[1]), "+f"(d[2]), "+f"(d[3])
        : "r"(a[0]), "r"(a[1]), "r"(a[2]), "r"(a[3]), "r"(b0), "r"(b1));
}

__global__ __launch_bounds__(256, 2)
void bgemm_split(const __nv_bfloat16* __restrict__ Ahi_g, const __nv_bfloat16* __restrict__ Alo_g,
                 const __nv_bfloat16* __restrict__ Bhi_g, const __nv_bfloat16* __restrict__ Blo_g,
                 const float* __restrict__ bias, float* __restrict__ C,
                 int M, int N, int K)
{
    extern __shared__ char gsm[];
    const int tid  = threadIdx.x;
    const int warp = tid >> 5;
    const int lane = tid & 31;
    const int g  = lane >> 2;
    const int tg = lane & 3;

    const int bm = blockIdx.y * GBM;
    const int bn = blockIdx.x * GBN;
    const int warp_m = (warp >> 1) * 32;
    const int warp_n = (warp & 1) * 64;

    // cp.async per-thread src/dst
    const int ar = tid >> 2, ac = (tid & 3) * 8;
    const int br = tid >> 4, bc = (tid & 15) * 8;
    const __nv_bfloat16* aih = Ahi_g + (size_t)(bm + ar) * K + ac;
    const __nv_bfloat16* ail = Alo_g + (size_t)(bm + ar) * K + ac;
    const __nv_bfloat16* bih = Bhi_g + (size_t)br * N + bn + bc;
    const __nv_bfloat16* bil = Blo_g + (size_t)br * N + bn + bc;
    const size_t a64 = (size_t)64 * K;
    const size_t b16 = (size_t)16 * N;

    const uint32_t smb = (uint32_t)__cvta_generic_to_shared(gsm);
    const uint32_t dA  = (uint32_t)(ar * ASTR + ac) * 2;
    const uint32_t dA2 = (uint32_t)((ar + 64) * ASTR + ac) * 2;
    const uint32_t dB  = (uint32_t)(br * BSTR + bc) * 2;
    const uint32_t dB2 = (uint32_t)((br + 16) * BSTR + bc) * 2;

    float acc[2][8][4];
    #pragma unroll
    for (int mt = 0; mt < 2; mt++)
        #pragma unroll
        for (int nt = 0; nt < 8; nt++)
            #pragma unroll
            for (int i = 0; i < 4; i++) acc[mt][nt][i] = 0.f;

    const int NK = K / GBK;

    // stage issue helper (as lambda-less macro)
    #define ISSUE_STAGE(s, kit) do {                                         \
        uint32_t so = smb + (uint32_t)(s) * STAGE_BYTES;                     \
        size_t ka = (size_t)(kit) * GBK;                                     \
        size_t kb = (size_t)(kit) * GBK * (size_t)N;                         \
        cpasync16(so + OFF_AHI + dA,  aih + ka);                             \
        cpasync16(so + OFF_AHI + dA2, aih + a64 + ka);                       \
        cpasync16(so + OFF_ALO + dA,  ail + ka);                             \
        cpasync16(so + OFF_ALO + dA2, ail + a64 + ka);                       \
        cpasync16(so + OFF_BHI + dB,  bih + kb);                             \
        cpasync16(so + OFF_BHI + dB2, bih + b16 + kb);                       \
        cpasync16(so + OFF_BLO + dB,  bil + kb);                             \
        cpasync16(so + OFF_BLO + dB2, bil + b16 + kb);                       \
        asm volatile("cp.async.commit_group;");                              \
    } while (0)

    ISSUE_STAGE(0, 0);

    const int a_r = lane & 15;
    const int a_c = (lane >> 4) * 8;

    for (int it = 0; it < NK; it++) {
        if (it + 1 < NK) {
            ISSUE_STAGE((it + 1) & 1, it + 1);
            asm volatile("cp.async.wait_group 1;");
        } else {
            asm volatile("cp.async.wait_group 0;");
        }
        __syncthreads();

        const uint32_t sb = smb + (uint32_t)(it & 1) * STAGE_BYTES;
        #pragma unroll
        for (int ks = 0; ks < 2; ks++) {
            const int kk = ks * 16;
            uint32_t ah[2][4], al[2][4];
            #pragma unroll
            for (int mt = 0; mt < 2; mt++) {
                uint32_t off = (uint32_t)((warp_m + mt * 16 + a_r) * ASTR + kk + a_c) * 2;
                ldsm4(ah[mt], sb + OFF_AHI + off);
                ldsm4(al[mt], sb + OFF_ALO + off);
            }
            #pragma unroll
            for (int np = 0; np < 4; np++) {
                uint32_t bh[4], bl[4];
                uint32_t off = (uint32_t)((kk + a_r) * BSTR + warp_n + np * 16 + a_c) * 2;
                ldsm4t(bh, sb + OFF_BHI + off);
                ldsm4t(bl, sb + OFF_BLO + off);
                #pragma unroll
                for (int half = 0; half < 2; half++) {
                    const int nt = np * 2 + half;
                    uint32_t b0h = bh[half * 2], b1h = bh[half * 2 + 1];
                    uint32_t b0l = bl[half * 2], b1l = bl[half * 2 + 1];
                    #pragma unroll
                    for (int mt = 0; mt < 2; mt++) {
                        mma_bf16(acc[mt][nt], ah[mt], b0h, b1h);   // hi*hi
                        mma_bf16(acc[mt][nt], ah[mt], b0l, b1l);   // hi*lo
                        mma_bf16(acc[mt][nt], al[mt], b0h, b1h);   // lo*hi
                    }
                }
            }
        }
        __syncthreads();
    }

    // epilogue: bias + store fp32
    #pragma unroll
    for (int nt = 0; nt < 8; nt++) {
        const int col = bn + warp_n + nt * 8 + 2 * tg;
        const float2 bs = *(const float2*)&bias[col];
        #pragma unroll
        for (int mt = 0; mt < 2; mt++) {
            const int row0 = bm + warp_m + mt * 16 + g;
            float2 o0 = make_float2(acc[mt][nt][0] + bs.x, acc[mt][nt][1] + bs.y);
            float2 o1 = make_float2(acc[mt][nt][2] + bs.x, acc[mt][nt][3] + bs.y);
            *(float2*)&C[(size_t)row0 * N + col]       = o0;
            *(float2*)&C[(size_t)(row0 + 8) * N + col] = o1;
        }
    }
    #undef ISSUE_STAGE
}

// ===========================================================================
// Tensor-core flash attention (tf32 mma.m16n8k8), causal, HD=64.
// CTA: 256 threads (8 warps), BQ=128 queries, KV tiles of 64.
// Writes y as bf16 hi/lo for the downstream split GEMM.
// ===========================================================================
#define AT_BQ   128
#define AT_BKV  64
#define KPAD    68
#define SCALE   0.125f

__device__ __forceinline__ float tf32r(float x) {
    uint32_t u;
    asm("cvt.rna.tf32.f32 %0, %1;" : "=r"(u) : "f"(x));
    return __uint_as_float(u);
}
__device__ __forceinline__ void mma_tf32(float d[4], const uint32_t a[4],
                                         uint32_t b0, uint32_t b1) {
    asm volatile(
        "mma.sync.aligned.m16n8k8.row.col.f32.tf32.tf32.f32 "
        "{%0,%1,%2,%3}, {%4,%5,%6,%7}, {%8,%9}, {%0,%1,%2,%3};"
        : "+f"(d[0]), "+f"(d[1]), "+f"(d[2]), "+f"(d[3])
        : "r"(a[0]), "r"(a[1]), "r"(a[2]), "r"(a[3]), "r"(b0), "r"(b1));
}

__global__ __launch_bounds__(256)
void attn_tc(const float* __restrict__ qkv,
             __nv_bfloat16* __restrict__ yhi, __nv_bfloat16* __restrict__ ylo)
{
    __shared__ float pool[AT_BQ * KPAD];    // Q staging; later Ks(rows 0..63) + Vs(64..127)
    float* Ks = pool;
    float* Vs = pool + AT_BKV * KPAD;

    const int b = blockIdx.z, h = blockIdx.y;
    const int qtile = gridDim.x - 1 - blockIdx.x;   // heavy tiles first
    const int q0 = qtile * AT_BQ;
    const int tid  = threadIdx.x;
    const int warp = tid >> 5;
    const int lane = tid & 31;
    const int g  = lane >> 2;
    const int tg = lane & 3;

    // ---- stage Q tile (tf32 bits, vectorized) ----
    {
        const float* qg = qkv + ((size_t)(b * Tn + q0)) * QKV_N + h * HDn;
        #pragma unroll
        for (int itr = 0; itr < 8; itr++) {
            int f = itr * 256 + tid;
            int r = f >> 4, c = (f & 15) << 2;
            float4 v = *(const float4*)(qg + (size_t)r * QKV_N + c);
            float4 t;
            t.x = tf32r(v.x); t.y = tf32r(v.y); t.z = tf32r(v.z); t.w = tf32r(v.w);
            *(float4*)&pool[r * KPAD + c] = t;
        }
    }
    __syncthreads();

    uint32_t Aq[8][4];
    {
        const int r0 = warp * 16 + g;
        #pragma unroll
        for (int k = 0; k < 8; k++) {
            Aq[k][0] = __float_as_uint(pool[(r0    ) * KPAD + k * 8 + tg    ]);
            Aq[k][1] = __float_as_uint(pool[(r0 + 8) * KPAD + k * 8 + tg    ]);
            Aq[k][2] = __float_as_uint(pool[(r0    ) * KPAD + k * 8 + tg + 4]);
            Aq[k][3] = __float_as_uint(pool[(r0 + 8) * KPAD + k * 8 + tg + 4]);
        }
    }
    __syncthreads();

    float O[8][4];
    #pragma unroll
    for (int nt = 0; nt < 8; nt++)
        #pragma unroll
        for (int i = 0; i < 4; i++) O[nt][i] = 0.f;

    float m0 = -INFINITY, m1 = -INFINITY;
    float l0 = 0.f, l1 = 0.f;

    const int qi0 = q0 + warp * 16 + g;
    const int qi1 = qi0 + 8;
    const int w_qmax = q0 + warp * 16 + 15;
    const int w_qmin = q0 + warp * 16;

    for (int kt = 0; kt < q0 + AT_BQ; kt += AT_BKV) {
        // ---- stage K and V tiles ----
        {
            const float* kg = qkv + ((size_t)(b * Tn + kt)) * QKV_N +     Cn + h * HDn;
            const float* vg = qkv + ((size_t)(b * Tn + kt)) * QKV_N + 2 * Cn + h * HDn;
            #pragma unroll
            for (int itr = 0; itr < 4; itr++) {
                int f = itr * 256 + tid;
                int r = f >> 4, c = (f & 15) << 2;
                float4 kv4 = *(const float4*)(kg + (size_t)r * QKV_N + c);
                float4 vv4 = *(const float4*)(vg + (size_t)r * QKV_N + c);
                float4 tk, tv;
                tk.x = tf32r(kv4.x); tk.y = tf32r(kv4.y); tk.z = tf32r(kv4.z); tk.w = tf32r(kv4.w);
                tv.x = tf32r(vv4.x); tv.y = tf32r(vv4.y); tv.z = tf32r(vv4.z); tv.w = tf32r(vv4.w);
                *(float4*)&Ks[r * KPAD + c] = tk;
                *(float4*)&Vs[r * KPAD + c] = tv;
            }
        }
        __syncthreads();

        if (kt <= w_qmax) {   // warp-uniform skip of fully-masked tiles
            // ---- S = Q @ K^T ----
            float S[8][4];
            #pragma unroll
            for (int nt = 0; nt < 8; nt++) {
                S[nt][0] = S[nt][1] = S[nt][2] = S[nt][3] = 0.f;
                #pragma unroll
                for (int k = 0; k < 8; k++) {
                    uint32_t b0 = __float_as_uint(Ks[(nt * 8 + g) * KPAD + k * 8 + tg    ]);
                    uint32_t b1 = __float_as_uint(Ks[(nt * 8 + g) * KPAD + k * 8 + tg + 4]);
                    mma_tf32(S[nt], Aq[k], b0, b1);
                }
            }

            const bool need_mask = (kt + AT_BKV - 1 > w_qmin);
            #pragma unroll
            for (int nt = 0; nt < 8; nt++) {
                int j0 = kt + nt * 8 + 2 * tg;
                int j1 = j0 + 1;
                S[nt][0] *= SCALE; S[nt][1] *= SCALE;
                S[nt][2] *= SCALE; S[nt][3] *= SCALE;
                if (need_mask) {
                    if (j0 > qi0) S[nt][0] = -INFINITY;
                    if (j1 > qi0) S[nt][1] = -INFINITY;
                    if (j0 > qi1) S[nt][2] = -INFINITY;
                    if (j1 > qi1) S[nt][3] = -INFINITY;
                }
            }

            // ---- online softmax ----
            float mc0 = -INFINITY, mc1 = -INFINITY;
            #pragma unroll
            for (int nt = 0; nt < 8; nt++) {
                mc0 = fmaxf(mc0, fmaxf(S[nt][0], S[nt][1]));
                mc1 = fmaxf(mc1, fmaxf(S[nt][2], S[nt][3]));
            }
            mc0 = fmaxf(mc0, __shfl_xor_sync(0xffffffffu, mc0, 1));
            mc0 = fmaxf(mc0, __shfl_xor_sync(0xffffffffu, mc0, 2));
            mc1 = fmaxf(mc1, __shfl_xor_sync(0xffffffffu, mc1, 1));
            mc1 = fmaxf(mc1, __shfl_xor_sync(0xffffffffu, mc1, 2));

            float mn0 = fmaxf(m0, mc0);
            float mn1 = fmaxf(m1, mc1);
            float corr0 = __expf(m0 - mn0);
            float corr1 = __expf(m1 - mn1);
            m0 = mn0; m1 = mn1;

            float ps0 = 0.f, ps1 = 0.f;
            #pragma unroll
            for (int nt = 0; nt < 8; nt++) {
                S[nt][0] = __expf(S[nt][0] - mn0);
                S[nt][1] = __expf(S[nt][1] - mn0);
                S[nt][2] = __expf(S[nt][2] - mn1);
                S[nt][3] = __expf(S[nt][3] - mn1);
                ps0 += S[nt][0] + S[nt][1];
                ps1 += S[nt][2] + S[nt][3];
            }
            ps0 += __shfl_xor_sync(0xffffffffu, ps0, 1);
            ps0 += __shfl_xor_sync(0xffffffffu, ps0, 2);
            ps1 += __shfl_xor_sync(0xffffffffu, ps1, 1);
            ps1 += __shfl_xor_sync(0xffffffffu, ps1, 2);
            l0 = l0 * corr0 + ps0;
            l1 = l1 * corr1 + ps1;

            #pragma unroll
            for (int nt = 0; nt < 8; nt++) {
                O[nt][0] *= corr0; O[nt][1] *= corr0;
                O[nt][2] *= corr1; O[nt][3] *= corr1;
            }

            // ---- O += P @ V ----
            const int src_lo = (lane & ~3) | (tg >> 1);
            const int src_hi = src_lo + 2;
            const bool odd = (tg & 1);
            #pragma unroll
            for (int kk = 0; kk < 8; kk++) {
                float p0 = S[kk][0], p1 = S[kk][1], p2 = S[kk][2], p3 = S[kk][3];
                float u, v;
                uint32_t Ap[4];
                u = __shfl_sync(0xffffffffu, p0, src_lo);
                v = __shfl_sync(0xffffffffu, p1, src_lo);
                Ap[0] = __float_as_uint(tf32r(odd ? v : u));
                u = __shfl_sync(0xffffffffu, p2, src_lo);
                v = __shfl_sync(0xffffffffu, p3, src_lo);
                Ap[1] = __float_as_uint(tf32r(odd ? v : u));
                u = __shfl_sync(0xffffffffu, p0, src_hi);
                v = __shfl_sync(0xffffffffu, p1, src_hi);
                Ap[2] = __float_as_uint(tf32r(odd ? v : u));
                u = __shfl_sync(0xffffffffu, p2, src_hi);
                v = __shfl_sync(0xffffffffu, p3, src_hi);
                Ap[3] = __float_as_uint(tf32r(odd ? v : u));

                #pragma unroll
                for (int dd = 0; dd < 8; dd++) {
                    uint32_t b0 = __float_as_uint(Vs[(kk * 8 + tg    ) * KPAD + dd * 8 + g]);
                    uint32_t b1 = __float_as_uint(Vs[(kk * 8 + tg + 4) * KPAD + dd * 8 + g]);
                    mma_tf32(O[dd], Ap, b0, b1);
                }
            }
        }
        __syncthreads();
    }

    // ---- finalize: divide by l, split to bf16 hi/lo, store ----
    const float inv0 = 1.f / l0;
    const float inv1 = 1.f / l1;
    const size_t row0 = (size_t)(b * Tn + qi0) * Cn + h * HDn;
    const size_t row1 = (size_t)(b * Tn + qi1) * Cn + h * HDn;
    #pragma unroll
    for (int nt = 0; nt < 8; nt++) {
        int c = nt * 8 + 2 * tg;
        float v00 = O[nt][0] * inv0, v01 = O[nt][1] * inv0;
        float v10 = O[nt][2] * inv1, v11 = O[nt][3] * inv1;
        __nv_bfloat16 h00 = __float2bfloat16(v00), h01 = __float2bfloat16(v01);
        __nv_bfloat16 h10 = __float2bfloat16(v10), h11 = __float2bfloat16(v11);
        *(__nv_bfloat162*)&yhi[row0 + c] = __nv_bfloat162(h00, h01);
        *(__nv_bfloat162*)&yhi[row1 + c] = __nv_bfloat162(h10, h11);
        *(__nv_bfloat162*)&ylo[row0 + c] = __nv_bfloat162(
            __float2bfloat16(v00 - __bfloat162float(h00)),
            __float2bfloat16(v01 - __bfloat162float(h01)));
        *(__nv_bfloat162*)&ylo[row1 + c] = __nv_bfloat162(
            __float2bfloat16(v10 - __bfloat162float(h10)),
            __float2bfloat16(v11 - __bfloat162float(h11)));
    }
}

// ---------------------------------------------------------------------------
// Launch
// ---------------------------------------------------------------------------
extern "C" void kernel_launch(void* const* d_in, const int* in_sizes, int n_in,
                              void* d_out, int out_size)
{
    const float* x      = (const float*)d_in[0];
    const float* w_attn = (const float*)d_in[1];
    const float* b_attn = (const float*)d_in[2];
    const float* w_proj = (const float*)d_in[3];
    const float* b_proj = (const float*)d_in[4];
    float* out = (float*)d_out;

    float* qkv_ptr; __nv_bfloat16 *xhi, *xlo, *wahi, *walo, *wphi, *wplo, *yhi, *ylo;
    cudaGetSymbolAddress((void**)&qkv_ptr, g_qkv);
    cudaGetSymbolAddress((void**)&xhi,  g_xhi);
    cudaGetSymbolAddress((void**)&xlo,  g_xlo);
    cudaGetSymbolAddress((void**)&wahi, g_wahi);
    cudaGetSymbolAddress((void**)&walo, g_walo);
    cudaGetSymbolAddress((void**)&wphi, g_wphi);
    cudaGetSymbolAddress((void**)&wplo, g_wplo);
    cudaGetSymbolAddress((void**)&yhi,  g_yhi);
    cudaGetSymbolAddress((void**)&ylo,  g_ylo);

    cudaFuncSetAttribute(bgemm_split, cudaFuncAttributeMaxDynamicSharedMemorySize, GEMM_SMEM);

    // 0) split inputs into bf16 hi/lo
    {
        int n4;
        n4 = (Mrows * Cn) / 4;
        split_kernel<<<(n4 + 255) / 256, 256>>>(x, xhi, xlo, n4);
        n4 = (Cn * QKV_N) / 4;
        split_kernel<<<(n4 + 255) / 256, 256>>>(w_attn, wahi, walo, n4);
        n4 = (Cn * Cn) / 4;
        split_kernel<<<(n4 + 255) / 256, 256>>>(w_proj, wphi, wplo, n4);
    }
    // 1) QKV projection
    {
        dim3 grid(QKV_N / GBN, Mrows / GBM);
        bgemm_split<<<grid, 256, GEMM_SMEM>>>(xhi, xlo, wahi, walo, b_attn,
                                              qkv_ptr, Mrows, QKV_N, Cn);
    }
    // 2) Causal attention (tf32 tensor cores), writes y hi/lo bf16
    {
        dim3 grid(Tn / AT_BQ, Hn, Bn);
        attn_tc<<<grid, 256>>>(qkv_ptr, yhi, ylo);
    }
    // 3) Output projection
    {
        dim3 grid(Cn / GBN, Mrows / GBM);
        bgemm_split<<<grid, 256, GEMM_SMEM>>>(yhi, ylo, wphi, wplo, b_proj,
                                              out, Mrows, Cn, Cn);
    }
}